// round 14
// baseline (speedup 1.0000x reference)
#include <cuda_runtime.h>
#include <cuda_bf16.h>
#include <cstdint>

#define B_ 8
#define C_ 512
#define CQ_ 64
#define N_ 4096
#define PR_ 640          // 64 Q rows + 64 K rows + 512 V rows
#define NSPLIT 8
#define NTILES 16        // projmma n-tiles (256 n each)
#define EPSV 1e-6f

// ---------------------------------------------------------------------------
// Scratch (__device__ globals; no allocations allowed anywhere)
// ---------------------------------------------------------------------------
__device__ float g_P[B_*PR_*N_];            // 83.9 MB projection output (fp32)
__device__ float g_Ksum[B_*CQ_];
__device__ float g_Vsum[B_*C_];
__device__ float g_part[NSPLIT*B_*CQ_*C_];  // split-K partials for matrix
__device__ float g_matrix[B_*CQ_*C_];
__device__ float g_bias[PR_];
__device__ float g_Wc[PR_*C_];              // combined W, tf32-rounded fp32
__device__ float g_rsPart[B_*576*NTILES];   // row-sum partials [b][row-64][ntile]

// ---------------------------------------------------------------------------
// Helpers (mma.sync tf32, sm_80+ PTX; lowers to HMMA on sm_103a)
// ---------------------------------------------------------------------------
__device__ __forceinline__ uint32_t smem_u32(const void* p){
    uint32_t a;
    asm("{ .reg .u64 t; cvta.to.shared.u64 t, %1; cvt.u32.u64 %0, t; }" : "=r"(a) : "l"(p));
    return a;
}
__device__ __forceinline__ float tf32_round(float f){
    uint32_t u;
    asm("cvt.rna.tf32.f32 %0, %1;" : "=r"(u) : "f"(f));
    return __uint_as_float(u);
}
__device__ __forceinline__ float4 round4(float4 v){
    v.x = tf32_round(v.x); v.y = tf32_round(v.y);
    v.z = tf32_round(v.z); v.w = tf32_round(v.w);
    return v;
}

#define LDSM_X4(r0,r1,r2,r3,addr) \
    asm volatile("ldmatrix.sync.aligned.m8n8.x4.shared.b16 {%0,%1,%2,%3}, [%4];" \
        : "=r"(r0),"=r"(r1),"=r"(r2),"=r"(r3) : "r"(addr))
#define MMA_TF32(c, a, b0v, b1v) \
    asm volatile("mma.sync.aligned.m16n8k8.row.col.f32.tf32.tf32.f32 " \
        "{%0,%1,%2,%3}, {%4,%5,%6,%7}, {%8,%9}, {%0,%1,%2,%3};" \
        : "+f"((c)[0]),"+f"((c)[1]),"+f"((c)[2]),"+f"((c)[3]) \
        : "r"((a)[0]),"r"((a)[1]),"r"((a)[2]),"r"((a)[3]),"r"(b0v),"r"(b1v))

// ---------------------------------------------------------------------------
// Conversion: combined W -> tf32-rounded fp32 + combined bias
// ---------------------------------------------------------------------------
__global__ void k_convW(const float* __restrict__ Wq, const float* __restrict__ bq,
                        const float* __restrict__ Wk, const float* __restrict__ bk,
                        const float* __restrict__ Wv, const float* __restrict__ bv)
{
    int id = blockIdx.x*256 + threadIdx.x;   // 0 .. 640*512-1
    int row = id >> 9, c = id & 511;
    float w;
    if (row < 64)        w = Wq[row*512 + c];
    else if (row < 128)  w = Wk[(row-64)*512 + c];
    else                 w = Wv[(row-128)*512 + c];
    g_Wc[id] = tf32_round(w);
    if (c == 0)
        g_bias[row] = (row < 64) ? bq[row] : ((row < 128) ? bk[row-64] : bv[row-128]);
}

// ---------------------------------------------------------------------------
// Kernel 1: QKV projection via mma.sync tf32, CTA tile 128m x 256n
// (halves x L2 traffic vs 128n), BK=16, double-buffered dynamic smem.
// Fused epilogue: bias, QK L2 norm (row-tile 0), row-sum partials.
// B staged directly from x with fused transpose + tf32 rounding (XOR swizzle).
// Dynamic smem layout (floats): SA[2][2560] @0, SB[2][5120] @5120.
// Epilogue aliases: SPart[4][256] @0, SRow[2][128] @1024 (SA dead by then).
// ---------------------------------------------------------------------------
#define BKC 16
#define SAS 20     // fp32 elems per smem row (16 + 4 pad)
#define PROJ_SMEM (15360*4)   // 61440 bytes

__global__ __launch_bounds__(256) void k_projmma(const float* __restrict__ x)
{
    extern __shared__ __align__(16) float sm[];
    float* SAb[2] = { sm,          sm + 2560 };
    float* SBb[2] = { sm + 5120,   sm + 10240 };
    float* SPart  = sm;           // [4][256]
    float* SRow   = sm + 1024;    // [2][128]

    const int tid = threadIdx.x, lane = tid & 31, wid = tid >> 5;
    const int b = blockIdx.z;
    const int row0 = blockIdx.y*128, n0 = blockIdx.x*256;
    const int ntile = blockIdx.x;
    const int warp_m = wid & 3, warp_n = wid >> 2;   // 4 m-tiles x 2 n-tiles(128)

    const int j = lane >> 3, r = lane & 7;
    const int aRow = warp_m*32 + (j & 1)*8 + r;
    const int aCol = (j >> 1)*4;
    const int bRow = warp_n*128 + (j >> 1)*8 + r;
    const int bK4j = (j & 1);

    const float* Ag = g_Wc + (size_t)row0*C_;
    const float* xb = x + (size_t)b*C_*N_;

    const int ngLo0 = tid & 7, cB0 = (tid >> 3) & 15, ngHi0 = tid >> 7;

    float acc[2][16][4];
    #pragma unroll
    for (int mi=0;mi<2;mi++)
        #pragma unroll
        for (int ni=0;ni<16;ni++)
            #pragma unroll
            for (int q=0;q<4;q++) acc[mi][ni][q] = 0.f;

    // ---- preload chunk 0 ----
    #pragma unroll
    for (int s=0;s<2;s++){
        int g = tid + s*256;
        int row = g >> 2, cg = g & 3;
        *(float4*)&SAb[0][row*SAS + cg*4] = *(const float4*)(Ag + (size_t)row*C_ + cg*4);
    }
    #pragma unroll
    for (int s=0;s<4;s++){
        int id = tid + s*256;
        int ngLo = id & 7, c = (id >> 3) & 15, ngHi = id >> 7;
        int ng = ngLo + ngHi*8;
        float4 v = *(const float4*)(xb + (size_t)c*N_ + n0 + ng*4);
        int k4 = c >> 2, kl = c & 3;
        #pragma unroll
        for (int i=0;i<4;i++){
            int n = ng*4 + i;
            int w = n*SAS + ((((n>>3)&3) ^ k4) << 2) + kl;
            SBb[0][w] = tf32_round(((const float*)&v)[i]);
        }
    }
    __syncthreads();

    const uint32_t saB[2] = { smem_u32(SAb[0]), smem_u32(SAb[1]) };
    const uint32_t sbB[2] = { smem_u32(SBb[0]), smem_u32(SBb[1]) };

    for (int ch = 0; ch < 32; ch++){
        const int buf = ch & 1;
        float4 pa[2], pb[4];
        if (ch + 1 < 32){
            int k0 = (ch+1)*BKC;
            #pragma unroll
            for (int s=0;s<2;s++){
                int g = tid + s*256;
                int row = g >> 2, cg = g & 3;
                pa[s] = *(const float4*)(Ag + (size_t)row*C_ + k0 + cg*4);
            }
            #pragma unroll
            for (int s=0;s<4;s++){
                int ng = ngLo0 + (ngHi0 + s*2)*8;
                pb[s] = *(const float4*)(xb + (size_t)(k0 + cB0)*N_ + n0 + ng*4);
            }
        }

        #pragma unroll
        for (int ks = 0; ks < 2; ks++){
            uint32_t a[2][4];
            #pragma unroll
            for (int mi=0;mi<2;mi++){
                uint32_t addr = saB[buf] + (uint32_t)(((aRow + mi*16)*SAS) + ks*8 + aCol)*4;
                LDSM_X4(a[mi][0],a[mi][1],a[mi][2],a[mi][3], addr);
            }
            const int k4f = ks*2 + bK4j;
            #pragma unroll
            for (int nt=0;nt<8;nt++){
                uint32_t bb[4];
                int nB = bRow + nt*16;
                uint32_t addr = sbB[buf] +
                    (uint32_t)(nB*SAS + ((((nB>>3)&3) ^ k4f) << 2))*4;
                LDSM_X4(bb[0],bb[1],bb[2],bb[3], addr);
                MMA_TF32(acc[0][nt*2+0], a[0], bb[0], bb[1]);
                MMA_TF32(acc[0][nt*2+1], a[0], bb[2], bb[3]);
                MMA_TF32(acc[1][nt*2+0], a[1], bb[0], bb[1]);
                MMA_TF32(acc[1][nt*2+1], a[1], bb[2], bb[3]);
            }
        }

        if (ch + 1 < 32){
            const int nb = buf ^ 1;
            #pragma unroll
            for (int s=0;s<2;s++){
                int g = tid + s*256;
                int row = g >> 2, cg = g & 3;
                *(float4*)&SAb[nb][row*SAS + cg*4] = pa[s];
            }
            const int k4 = cB0 >> 2, kl = cB0 & 3;
            #pragma unroll
            for (int s=0;s<4;s++){
                int ng = ngLo0 + (ngHi0 + s*2)*8;
                #pragma unroll
                for (int i=0;i<4;i++){
                    int n = ng*4 + i;
                    int w = n*SAS + ((((n>>3)&3) ^ k4) << 2) + kl;
                    SBb[nb][w] = tf32_round(((const float*)&pb[s])[i]);
                }
            }
        }
        __syncthreads();
    }

    // ===== fused epilogue =====
    const bool isQK = (row0 == 0);

    #pragma unroll
    for (int mi=0;mi<2;mi++){
        int r_lo = row0 + warp_m*32 + mi*16 + (lane >> 2);
        float bl = g_bias[r_lo], bh = g_bias[r_lo + 8];
        #pragma unroll
        for (int ni=0;ni<16;ni++){
            acc[mi][ni][0] += bl; acc[mi][ni][1] += bl;
            acc[mi][ni][2] += bh; acc[mi][ni][3] += bh;
        }
    }

    if (isQK){
        #pragma unroll
        for (int ni=0;ni<16;ni++)
            #pragma unroll
            for (int p=0;p<2;p++){
                float s = acc[0][ni][p]*acc[0][ni][p] + acc[0][ni][p+2]*acc[0][ni][p+2]
                        + acc[1][ni][p]*acc[1][ni][p] + acc[1][ni][p+2]*acc[1][ni][p+2];
                s += __shfl_xor_sync(0xFFFFFFFF, s, 4);
                s += __shfl_xor_sync(0xFFFFFFFF, s, 8);
                s += __shfl_xor_sync(0xFFFFFFFF, s, 16);
                if ((lane >> 2) == 0)
                    SPart[warp_m*256 + warp_n*128 + ni*8 + (lane&3)*2 + p] = s;
            }
    }
    __syncthreads();
    if (isQK){
        const int base = (warp_m < 2) ? 0 : 2;
        #pragma unroll
        for (int ni=0;ni<16;ni++)
            #pragma unroll
            for (int p=0;p<2;p++){
                int col = warp_n*128 + ni*8 + (lane&3)*2 + p;
                float inv = rsqrtf(SPart[base*256 + col] + SPart[(base+1)*256 + col]);
                acc[0][ni][p]   *= inv; acc[0][ni][p+2] *= inv;
                acc[1][ni][p]   *= inv; acc[1][ni][p+2] *= inv;
            }
    }

    {
        #pragma unroll
        for (int mi=0;mi<2;mi++)
            #pragma unroll
            for (int h=0;h<2;h++){
                float s = 0.f;
                #pragma unroll
                for (int ni=0;ni<16;ni++) s += acc[mi][ni][2*h] + acc[mi][ni][2*h+1];
                s += __shfl_xor_sync(0xFFFFFFFF, s, 1);
                s += __shfl_xor_sync(0xFFFFFFFF, s, 2);
                if ((lane & 3) == 0)
                    SRow[warp_n*128 + warp_m*32 + mi*16 + h*8 + (lane>>2)] = s;
            }
    }
    __syncthreads();
    if (tid < 128){
        int grow = row0 + tid;
        if (grow >= 64)
            g_rsPart[((size_t)b*576 + (grow - 64))*NTILES + ntile]
                = SRow[tid] + SRow[128 + tid];
    }

    const int base_col = n0 + warp_n*128 + (lane & 3)*2;
    #pragma unroll
    for (int mi=0;mi<2;mi++){
        int r_lo = row0 + warp_m*32 + mi*16 + (lane >> 2);
        int r_hi = r_lo + 8;
        float* p_lo = g_P + ((size_t)b*PR_ + r_lo)*N_;
        float* p_hi = g_P + ((size_t)b*PR_ + r_hi)*N_;
        #pragma unroll
        for (int ni=0;ni<16;ni++){
            int col = base_col + ni*8;
            *(float2*)(p_lo + col) = make_float2(acc[mi][ni][0], acc[mi][ni][1]);
            *(float2*)(p_hi + col) = make_float2(acc[mi][ni][2], acc[mi][ni][3]);
        }
    }
}

// ---------------------------------------------------------------------------
// Kernel 2: reduce row-sum partials -> Ksum (rows 0..63) / Vsum (rows 64..575)
// ---------------------------------------------------------------------------
__global__ void k_rsreduce()
{
    int idx = blockIdx.x*256 + threadIdx.x;      // 0 .. 8*576-1
    if (idx >= B_*576) return;
    int b = idx / 576, row = idx % 576;
    const float* p = g_rsPart + (size_t)idx*NTILES;
    float s = 0.f;
    #pragma unroll
    for (int t = 0; t < NTILES; t++) s += p[t];
    if (row < 64) g_Ksum[b*CQ_ + row]     = s;
    else          g_Vsum[b*C_ + row - 64] = s;
}

// ---------------------------------------------------------------------------
// Kernel 3: matrix partials via TF32 mma.
// part[sp,b,m,c] = sum_{n in split} Kn[m,n]*V[c,n]
// ---------------------------------------------------------------------------
__global__ __launch_bounds__(256) void k_matmma()
{
    __shared__ __align__(16) float SA[2][64*SAS];
    __shared__ __align__(16) float SB[2][128*SAS];

    const int tid = threadIdx.x, lane = tid & 31, wid = tid >> 5;
    const int ct = blockIdx.x, sp = blockIdx.y, b = blockIdx.z;
    const int wm = wid & 1, wn = wid >> 1;

    const int j = lane >> 3, r = lane & 7;
    const int aRow = wm*32 + (j & 1)*8 + r;
    const int aCol = (j >> 1)*4;
    const int bRow = wn*32 + (j >> 1)*8 + r;
    const int bCol = (j & 1)*4;

    const float* Ag = g_P + ((size_t)b*PR_ + 64)*N_ + sp*512;            // Kn
    const float* Bg = g_P + ((size_t)b*PR_ + 128 + ct*128)*N_ + sp*512;  // V

    float acc[2][4][4];
    #pragma unroll
    for (int mi=0;mi<2;mi++)
        #pragma unroll
        for (int ni=0;ni<4;ni++)
            #pragma unroll
            for (int q=0;q<4;q++) acc[mi][ni][q] = 0.f;

    {
        int row = tid >> 2, cg = tid & 3;
        *(float4*)&SA[0][row*SAS + cg*4] = round4(*(const float4*)(Ag + (size_t)row*N_ + cg*4));
        #pragma unroll
        for (int s=0;s<2;s++){
            int g = tid + s*256;
            int br = g >> 2, bcg = g & 3;
            *(float4*)&SB[0][br*SAS + bcg*4] = round4(*(const float4*)(Bg + (size_t)br*N_ + bcg*4));
        }
    }
    __syncthreads();

    const uint32_t saB[2] = { smem_u32(&SA[0][0]), smem_u32(&SA[1][0]) };
    const uint32_t sbB[2] = { smem_u32(&SB[0][0]), smem_u32(&SB[1][0]) };

    for (int ch = 0; ch < 32; ch++){
        const int buf = ch & 1;
        float4 pa, pb[2];
        if (ch + 1 < 32){
            int k0 = (ch+1)*BKC;
            int row = tid >> 2, cg = tid & 3;
            pa = *(const float4*)(Ag + (size_t)row*N_ + k0 + cg*4);
            #pragma unroll
            for (int s=0;s<2;s++){
                int g = tid + s*256;
                int br = g >> 2, bcg = g & 3;
                pb[s] = *(const float4*)(Bg + (size_t)br*N_ + k0 + bcg*4);
            }
        }

        #pragma unroll
        for (int ks = 0; ks < 2; ks++){
            uint32_t a[2][4], bb[2][4];
            #pragma unroll
            for (int mi=0;mi<2;mi++){
                uint32_t addr = saB[buf] + (uint32_t)((aRow + mi*16)*SAS + ks*8 + aCol)*4;
                LDSM_X4(a[mi][0],a[mi][1],a[mi][2],a[mi][3], addr);
            }
            #pragma unroll
            for (int nt=0;nt<2;nt++){
                uint32_t addr = sbB[buf] + (uint32_t)(((bRow + nt*16)*SAS) + ks*8 + bCol)*4;
                LDSM_X4(bb[nt][0],bb[nt][1],bb[nt][2],bb[nt][3], addr);
            }
            #pragma unroll
            for (int mi=0;mi<2;mi++)
                #pragma unroll
                for (int nt=0;nt<2;nt++){
                    MMA_TF32(acc[mi][nt*2+0], a[mi], bb[nt][0], bb[nt][1]);
                    MMA_TF32(acc[mi][nt*2+1], a[mi], bb[nt][2], bb[nt][3]);
                }
        }

        if (ch + 1 < 32){
            const int nb = buf ^ 1;
            int row = tid >> 2, cg = tid & 3;
            *(float4*)&SA[nb][row*SAS + cg*4] = round4(pa);
            #pragma unroll
            for (int s=0;s<2;s++){
                int g = tid + s*256;
                int br = g >> 2, bcg = g & 3;
                *(float4*)&SB[nb][br*SAS + bcg*4] = round4(pb[s]);
            }
        }
        __syncthreads();
    }

    const int base_col = ct*128 + wn*32 + (lane & 3)*2;
    float* pbase = g_part + (((size_t)sp*B_ + b)*CQ_)*C_;
    #pragma unroll
    for (int mi=0;mi<2;mi++){
        int m_lo = wm*32 + mi*16 + (lane >> 2);
        int m_hi = m_lo + 8;
        #pragma unroll
        for (int ni=0;ni<4;ni++){
            int col = base_col + ni*8;
            *(float2*)(pbase + (size_t)m_lo*C_ + col) = make_float2(acc[mi][ni][0], acc[mi][ni][1]);
            *(float2*)(pbase + (size_t)m_hi*C_ + col) = make_float2(acc[mi][ni][2], acc[mi][ni][3]);
        }
    }
}

// float4 reduction of split-K partials (deterministic fixed order)
__global__ void k_matreduce()
{
    int idx = (blockIdx.x*256 + threadIdx.x)*4;
    float4 s = *(const float4*)(g_part + idx);
    #pragma unroll
    for (int sp = 1; sp < NSPLIT; sp++){
        float4 v = *(const float4*)(g_part + (size_t)sp*B_*CQ_*C_ + idx);
        s.x += v.x; s.y += v.y; s.z += v.z; s.w += v.w;
    }
    *(float4*)(g_matrix + idx) = s;
}

// ---------------------------------------------------------------------------
// Kernel 4 via TF32 mma: out[b,c,n] = g*tailor[n]*(Vsum[c] + sum_m Qn[m,n]*M[m,c])
// CTA covers 64c x 128n (two 64n passes, SA + A-frags reused).  tailor is
// computed IN-KERNEL per n-pass from the staged (tf32) Qn tile + Ksum.
// ---------------------------------------------------------------------------
#define FS 68    // 64 + 4 pad -> conflict-free LDSM

__global__ __launch_bounds__(256) void k_finalmma(const float* __restrict__ gamma,
                                                  float* __restrict__ out)
{
    __shared__ __align__(16) float SA[64*FS];   // [c_local][m]
    __shared__ __align__(16) float SB[64*FS];   // [n_local][m]
    __shared__ float SKsum[64];
    __shared__ float STail[64];

    const int tid = threadIdx.x, lane = tid & 31, wid = tid >> 5;
    const int n0 = blockIdx.x*128, c0 = blockIdx.y*64, b = blockIdx.z;
    const int wm = wid & 3, wn = wid >> 2;      // warp tile 16c x 32n per pass

    if (tid < 64) SKsum[tid] = g_Ksum[b*CQ_ + tid] + EPSV;

    // stage SA (matrix tile, transposed [c][m])
    #pragma unroll
    for (int s=0;s<4;s++){
        int id = tid + s*256;
        int m = id & 63, cg = id >> 6;
        float4 v = round4(*(const float4*)(g_matrix + ((size_t)b*CQ_ + m)*C_ + c0 + cg*4));
        SA[(cg*4+0)*FS + m] = v.x;
        SA[(cg*4+1)*FS + m] = v.y;
        SA[(cg*4+2)*FS + m] = v.z;
        SA[(cg*4+3)*FS + m] = v.w;
    }
    // stage SB for n-half 0
    #pragma unroll
    for (int s=0;s<4;s++){
        int id = tid + s*256;
        int m = id & 63, ng = id >> 6;
        float4 v = round4(*(const float4*)(g_P + ((size_t)b*PR_ + m)*N_ + n0 + ng*4));
        SB[(ng*4+0)*FS + m] = v.x;
        SB[(ng*4+1)*FS + m] = v.y;
        SB[(ng*4+2)*FS + m] = v.z;
        SB[(ng*4+3)*FS + m] = v.w;
    }
    __syncthreads();

    const uint32_t saB = smem_u32(&SA[0]);
    const uint32_t sbB = smem_u32(&SB[0]);
    const int j = lane >> 3, r = lane & 7;
    const int aRow = wm*16 + (j & 1)*8 + r;
    const int aCol = (j >> 1)*4;
    const int bRow = wn*32 + (j >> 1)*8 + r;
    const int bCol = (j & 1)*4;

    // hoist all A fragments (SA reused by both passes)
    uint32_t a[8][4];
    #pragma unroll
    for (int ks = 0; ks < 8; ks++){
        uint32_t addr = saB + (uint32_t)(aRow*FS + ks*8 + aCol)*4;
        LDSM_X4(a[ks][0],a[ks][1],a[ks][2],a[ks][3], addr);
    }

    const float g = gamma[0];
    const int c_lo = c0 + wm*16 + (lane >> 2);
    const int c_hi = c_lo + 8;
    const float vs_lo = g_Vsum[b*C_ + c_lo];
    const float vs_hi = g_Vsum[b*C_ + c_hi];
    float* o_lo = out + ((size_t)b*C_ + c_lo)*N_;
    float* o_hi = out + ((size_t)b*C_ + c_hi)*N_;

    #pragma unroll
    for (int np = 0; np < 2; np++){
        // tailor for this n-half from staged Qn tile + Ksum
        {
            int nl = tid >> 2, part = tid & 3;
            float s = 0.f;
            #pragma unroll
            for (int i = 0; i < 16; i++){
                int m = part*16 + i;
                s = fmaf(SB[nl*FS + m], SKsum[m], s);
            }
            s += __shfl_xor_sync(0xFFFFFFFF, s, 1);
            s += __shfl_xor_sync(0xFFFFFFFF, s, 2);
            if (part == 0) STail[nl] = 1.f / (4096.f + s);
        }
        __syncthreads();

        float acc[4][4];
        #pragma unroll
        for (int ni=0;ni<4;ni++)
            #pragma unroll
            for (int q=0;q<4;q++) acc[ni][q] = 0.f;

        #pragma unroll
        for (int ks = 0; ks < 8; ks++){
            uint32_t bb[2][4];
            #pragma unroll
            for (int nt=0;nt<2;nt++){
                uint32_t addr = sbB + (uint32_t)((bRow + nt*16)*FS + ks*8 + bCol)*4;
                LDSM_X4(bb[nt][0],bb[nt][1],bb[nt][2],bb[nt][3], addr);
            }
            #pragma unroll
            for (int nt=0;nt<2;nt++){
                MMA_TF32(acc[nt*2+0], a[ks], bb[nt][0], bb[nt][1]);
                MMA_TF32(acc[nt*2+1], a[ks], bb[nt][2], bb[nt][3]);
            }
        }

        const int nloc0 = wn*32 + (lane & 3)*2;
        const int base_n = n0 + np*64 + nloc0;
        #pragma unroll
        for (int ni=0;ni<4;ni++){
            int n = base_n + ni*8;
            float t0 = STail[nloc0 + ni*8]*g, t1 = STail[nloc0 + ni*8 + 1]*g;
            *(float2*)(o_lo + n) = make_float2(t0*(vs_lo + acc[ni][0]), t1*(vs_lo + acc[ni][1]));
            *(float2*)(o_hi + n) = make_float2(t0*(vs_hi + acc[ni][2]), t1*(vs_hi + acc[ni][3]));
        }

        if (np == 0){
            __syncthreads();
            // restage SB for n-half 1
            #pragma unroll
            for (int s=0;s<4;s++){
                int id = tid + s*256;
                int m = id & 63, ng = id >> 6;
                float4 v = round4(*(const float4*)(g_P + ((size_t)b*PR_ + m)*N_ + n0 + 64 + ng*4));
                SB[(ng*4+0)*FS + m] = v.x;
                SB[(ng*4+1)*FS + m] = v.y;
                SB[(ng*4+2)*FS + m] = v.z;
                SB[(ng*4+3)*FS + m] = v.w;
            }
            __syncthreads();
        }
    }
}

// ---------------------------------------------------------------------------
extern "C" void kernel_launch(void* const* d_in, const int* in_sizes, int n_in,
                              void* d_out, int out_size)
{
    const float* x     = (const float*)d_in[0];
    const float* Wq    = (const float*)d_in[1];
    const float* bq    = (const float*)d_in[2];
    const float* Wk    = (const float*)d_in[3];
    const float* bk    = (const float*)d_in[4];
    const float* Wv    = (const float*)d_in[5];
    const float* bv    = (const float*)d_in[6];
    const float* gamma = (const float*)d_in[7];
    float* out = (float*)d_out;

    cudaFuncSetAttribute(k_projmma, cudaFuncAttributeMaxDynamicSharedMemorySize, PROJ_SMEM);

    k_convW    <<<(PR_*C_)/256, 256>>>(Wq, bq, Wk, bk, Wv, bv);
    k_projmma  <<<dim3(16,5,8), 256, PROJ_SMEM>>>(x);
    k_rsreduce <<<18, 256>>>();
    k_matmma   <<<dim3(4,8,8),  256>>>();
    k_matreduce<<<(B_*CQ_*C_)/1024, 256>>>();
    k_finalmma <<<dim3(32,8,8), 256>>>(gamma, out);
}

// round 15
// speedup vs baseline: 1.1489x; 1.1489x over previous
#include <cuda_runtime.h>
#include <cuda_bf16.h>
#include <cstdint>

#define B_ 8
#define C_ 512
#define CQ_ 64
#define N_ 4096
#define PR_ 640          // 64 Q rows + 64 K rows + 512 V rows
#define NSPLIT 8
#define NTILES 32        // projmma n-tiles (128 n each)
#define EPSV 1e-6f

// ---------------------------------------------------------------------------
// Scratch (__device__ globals; no allocations allowed anywhere)
// ---------------------------------------------------------------------------
__device__ float g_P[B_*PR_*N_];            // 83.9 MB projection output (fp32)
__device__ float g_Ksum[B_*CQ_];
__device__ float g_Vsum[B_*C_];
__device__ float g_part[NSPLIT*B_*CQ_*C_];  // split-K partials for matrix
__device__ float g_matrix[B_*CQ_*C_];
__device__ float g_bias[PR_];
__device__ float g_Wc[PR_*C_];              // combined W, tf32-rounded fp32
__device__ float g_rsPart[B_*576*NTILES];   // row-sum partials [b][row-64][ntile]

// ---------------------------------------------------------------------------
// Helpers (mma.sync tf32, sm_80+ PTX; lowers to HMMA on sm_103a)
// ---------------------------------------------------------------------------
__device__ __forceinline__ uint32_t smem_u32(const void* p){
    uint32_t a;
    asm("{ .reg .u64 t; cvta.to.shared.u64 t, %1; cvt.u32.u64 %0, t; }" : "=r"(a) : "l"(p));
    return a;
}
__device__ __forceinline__ float tf32_round(float f){
    uint32_t u;
    asm("cvt.rna.tf32.f32 %0, %1;" : "=r"(u) : "f"(f));
    return __uint_as_float(u);
}
__device__ __forceinline__ float4 round4(float4 v){
    v.x = tf32_round(v.x); v.y = tf32_round(v.y);
    v.z = tf32_round(v.z); v.w = tf32_round(v.w);
    return v;
}

#define LDSM_X4(r0,r1,r2,r3,addr) \
    asm volatile("ldmatrix.sync.aligned.m8n8.x4.shared.b16 {%0,%1,%2,%3}, [%4];" \
        : "=r"(r0),"=r"(r1),"=r"(r2),"=r"(r3) : "r"(addr))
#define MMA_TF32(c, a, b0v, b1v) \
    asm volatile("mma.sync.aligned.m16n8k8.row.col.f32.tf32.tf32.f32 " \
        "{%0,%1,%2,%3}, {%4,%5,%6,%7}, {%8,%9}, {%0,%1,%2,%3};" \
        : "+f"((c)[0]),"+f"((c)[1]),"+f"((c)[2]),"+f"((c)[3]) \
        : "r"((a)[0]),"r"((a)[1]),"r"((a)[2]),"r"((a)[3]),"r"(b0v),"r"(b1v))

// ---------------------------------------------------------------------------
// Conversion: combined W -> tf32-rounded fp32 + combined bias
// ---------------------------------------------------------------------------
__global__ void k_convW(const float* __restrict__ Wq, const float* __restrict__ bq,
                        const float* __restrict__ Wk, const float* __restrict__ bk,
                        const float* __restrict__ Wv, const float* __restrict__ bv)
{
    int id = blockIdx.x*256 + threadIdx.x;   // 0 .. 640*512-1
    int row = id >> 9, c = id & 511;
    float w;
    if (row < 64)        w = Wq[row*512 + c];
    else if (row < 128)  w = Wk[(row-64)*512 + c];
    else                 w = Wv[(row-128)*512 + c];
    g_Wc[id] = tf32_round(w);
    if (c == 0)
        g_bias[row] = (row < 64) ? bq[row] : ((row < 128) ? bk[row-64] : bv[row-128]);
}

// ---------------------------------------------------------------------------
// Kernel 1: QKV projection via mma.sync tf32 (R13 config: 128m x 128n, 64 acc
// regs — fits without spills).  FUSED epilogue: bias, QK L2 norm (row-tile 0),
// row-sum partials.  B staged directly from x with fused transpose + tf32
// rounding (XOR swizzle on the 16B k-group).
// ---------------------------------------------------------------------------
#define BKC 16
#define SAS 20     // fp32 elems per smem row (16 + 4 pad)

__global__ __launch_bounds__(256) void k_projmma(const float* __restrict__ x)
{
    __shared__ __align__(16) float SA[2][128*SAS];
    __shared__ __align__(16) float SB[2][128*SAS];
    __shared__ float SPart[4][128];   // col sum-of-squares partials by warp_m
    __shared__ float SRow[2][128];    // row-sum partials by warp_n

    const int tid = threadIdx.x, lane = tid & 31, wid = tid >> 5;
    const int b = blockIdx.z;
    const int row0 = blockIdx.y*128, n0 = blockIdx.x*128;
    const int ntile = blockIdx.x;
    const int warp_m = wid & 3, warp_n = wid >> 2;

    const int j = lane >> 3, r = lane & 7;
    const int aRow = warp_m*32 + (j & 1)*8 + r;
    const int aCol = (j >> 1)*4;
    const int bRow = warp_n*64 + (j >> 1)*8 + r;
    const int bK4j = (j & 1);

    const float* Ag = g_Wc + (size_t)row0*C_;
    const float* xb = x + (size_t)b*C_*N_;

    const int ngLo0 = tid & 7, cB0 = (tid >> 3) & 15, ngHi0 = tid >> 7;

    float acc[2][8][4];
    #pragma unroll
    for (int mi=0;mi<2;mi++)
        #pragma unroll
        for (int ni=0;ni<8;ni++)
            #pragma unroll
            for (int q=0;q<4;q++) acc[mi][ni][q] = 0.f;

    // ---- preload chunk 0 ----
    #pragma unroll
    for (int s=0;s<2;s++){
        int g = tid + s*256;
        int row = g >> 2, cg = g & 3;
        *(float4*)&SA[0][row*SAS + cg*4] = *(const float4*)(Ag + (size_t)row*C_ + cg*4);
    }
    #pragma unroll
    for (int s=0;s<2;s++){
        int id = tid + s*256;
        int ngLo = id & 7, c = (id >> 3) & 15, ngHi = id >> 7;
        int ng = ngLo + ngHi*8;
        float4 v = *(const float4*)(xb + (size_t)c*N_ + n0 + ng*4);
        int k4 = c >> 2, kl = c & 3;
        #pragma unroll
        for (int i=0;i<4;i++){
            int n = ng*4 + i;
            int w = n*SAS + ((((n>>3)&3) ^ k4) << 2) + kl;
            SB[0][w] = tf32_round(((const float*)&v)[i]);
        }
    }
    __syncthreads();

    const uint32_t saB[2] = { smem_u32(&SA[0][0]), smem_u32(&SA[1][0]) };
    const uint32_t sbB[2] = { smem_u32(&SB[0][0]), smem_u32(&SB[1][0]) };

    for (int ch = 0; ch < 32; ch++){
        const int buf = ch & 1;
        float4 pa[2], pb[2];
        if (ch + 1 < 32){
            int k0 = (ch+1)*BKC;
            #pragma unroll
            for (int s=0;s<2;s++){
                int g = tid + s*256;
                int row = g >> 2, cg = g & 3;
                pa[s] = *(const float4*)(Ag + (size_t)row*C_ + k0 + cg*4);
            }
            #pragma unroll
            for (int s=0;s<2;s++){
                int ng = ngLo0 + (ngHi0 + s*2)*8;
                pb[s] = *(const float4*)(xb + (size_t)(k0 + cB0)*N_ + n0 + ng*4);
            }
        }

        #pragma unroll
        for (int ks = 0; ks < 2; ks++){
            uint32_t a[2][4], bb[4][4];
            #pragma unroll
            for (int mi=0;mi<2;mi++){
                uint32_t addr = saB[buf] + (uint32_t)(((aRow + mi*16)*SAS) + ks*8 + aCol)*4;
                LDSM_X4(a[mi][0],a[mi][1],a[mi][2],a[mi][3], addr);
            }
            const int k4f = ks*2 + bK4j;
            #pragma unroll
            for (int nt=0;nt<4;nt++){
                int nB = bRow + nt*16;
                uint32_t addr = sbB[buf] +
                    (uint32_t)(nB*SAS + ((((nB>>3)&3) ^ k4f) << 2))*4;
                LDSM_X4(bb[nt][0],bb[nt][1],bb[nt][2],bb[nt][3], addr);
            }
            #pragma unroll
            for (int mi=0;mi<2;mi++)
                #pragma unroll
                for (int nt=0;nt<4;nt++){
                    MMA_TF32(acc[mi][nt*2+0], a[mi], bb[nt][0], bb[nt][1]);
                    MMA_TF32(acc[mi][nt*2+1], a[mi], bb[nt][2], bb[nt][3]);
                }
        }

        if (ch + 1 < 32){
            const int nb = buf ^ 1;
            #pragma unroll
            for (int s=0;s<2;s++){
                int g = tid + s*256;
                int row = g >> 2, cg = g & 3;
                *(float4*)&SA[nb][row*SAS + cg*4] = pa[s];
            }
            const int k4 = cB0 >> 2, kl = cB0 & 3;
            #pragma unroll
            for (int s=0;s<2;s++){
                int ng = ngLo0 + (ngHi0 + s*2)*8;
                #pragma unroll
                for (int i=0;i<4;i++){
                    int n = ng*4 + i;
                    int w = n*SAS + ((((n>>3)&3) ^ k4) << 2) + kl;
                    SB[nb][w] = tf32_round(((const float*)&pb[s])[i]);
                }
            }
        }
        __syncthreads();
    }

    // ===== fused epilogue =====
    const bool isQK = (row0 == 0);

    #pragma unroll
    for (int mi=0;mi<2;mi++){
        int r_lo = row0 + warp_m*32 + mi*16 + (lane >> 2);
        float bl = g_bias[r_lo], bh = g_bias[r_lo + 8];
        #pragma unroll
        for (int ni=0;ni<8;ni++){
            acc[mi][ni][0] += bl; acc[mi][ni][1] += bl;
            acc[mi][ni][2] += bh; acc[mi][ni][3] += bh;
        }
    }

    if (isQK){
        float cs[8][2];
        #pragma unroll
        for (int ni=0;ni<8;ni++)
            #pragma unroll
            for (int p=0;p<2;p++){
                float s = acc[0][ni][p]*acc[0][ni][p] + acc[0][ni][p+2]*acc[0][ni][p+2]
                        + acc[1][ni][p]*acc[1][ni][p] + acc[1][ni][p+2]*acc[1][ni][p+2];
                s += __shfl_xor_sync(0xFFFFFFFF, s, 4);
                s += __shfl_xor_sync(0xFFFFFFFF, s, 8);
                s += __shfl_xor_sync(0xFFFFFFFF, s, 16);
                cs[ni][p] = s;
            }
        if ((lane >> 2) == 0){
            #pragma unroll
            for (int ni=0;ni<8;ni++)
                #pragma unroll
                for (int p=0;p<2;p++)
                    SPart[warp_m][warp_n*64 + ni*8 + (lane&3)*2 + p] = cs[ni][p];
        }
    }
    __syncthreads();
    if (isQK){
        const int base = (warp_m < 2) ? 0 : 2;
        #pragma unroll
        for (int ni=0;ni<8;ni++)
            #pragma unroll
            for (int p=0;p<2;p++){
                int col = warp_n*64 + ni*8 + (lane&3)*2 + p;
                float inv = rsqrtf(SPart[base][col] + SPart[base+1][col]);
                acc[0][ni][p]   *= inv; acc[0][ni][p+2] *= inv;
                acc[1][ni][p]   *= inv; acc[1][ni][p+2] *= inv;
            }
    }

    {
        float rs[2][2];
        #pragma unroll
        for (int mi=0;mi<2;mi++)
            #pragma unroll
            for (int h=0;h<2;h++){
                float s = 0.f;
                #pragma unroll
                for (int ni=0;ni<8;ni++) s += acc[mi][ni][2*h] + acc[mi][ni][2*h+1];
                s += __shfl_xor_sync(0xFFFFFFFF, s, 1);
                s += __shfl_xor_sync(0xFFFFFFFF, s, 2);
                rs[mi][h] = s;
            }
        if ((lane & 3) == 0){
            #pragma unroll
            for (int mi=0;mi<2;mi++)
                #pragma unroll
                for (int h=0;h<2;h++)
                    SRow[warp_n][warp_m*32 + mi*16 + h*8 + (lane>>2)] = rs[mi][h];
        }
    }
    __syncthreads();
    if (tid < 128){
        int grow = row0 + tid;
        if (grow >= 64)
            g_rsPart[((size_t)b*576 + (grow - 64))*NTILES + ntile]
                = SRow[0][tid] + SRow[1][tid];
    }

    const int base_col = n0 + warp_n*64 + (lane & 3)*2;
    #pragma unroll
    for (int mi=0;mi<2;mi++){
        int r_lo = row0 + warp_m*32 + mi*16 + (lane >> 2);
        int r_hi = r_lo + 8;
        float* p_lo = g_P + ((size_t)b*PR_ + r_lo)*N_;
        float* p_hi = g_P + ((size_t)b*PR_ + r_hi)*N_;
        #pragma unroll
        for (int ni=0;ni<8;ni++){
            int col = base_col + ni*8;
            *(float2*)(p_lo + col) = make_float2(acc[mi][ni][0], acc[mi][ni][1]);
            *(float2*)(p_hi + col) = make_float2(acc[mi][ni][2], acc[mi][ni][3]);
        }
    }
}

// ---------------------------------------------------------------------------
// Kernel 2: reduce row-sum partials -> Ksum (rows 0..63) / Vsum (rows 64..575)
// ---------------------------------------------------------------------------
__global__ void k_rsreduce()
{
    int idx = blockIdx.x*256 + threadIdx.x;      // 0 .. 8*576-1
    if (idx >= B_*576) return;
    int b = idx / 576, row = idx % 576;
    const float* p = g_rsPart + (size_t)idx*NTILES;
    float s = 0.f;
    #pragma unroll
    for (int t = 0; t < NTILES; t++) s += p[t];
    if (row < 64) g_Ksum[b*CQ_ + row]     = s;
    else          g_Vsum[b*C_ + row - 64] = s;
}

// ---------------------------------------------------------------------------
// Kernel 3: matrix partials via TF32 mma.
// part[sp,b,m,c] = sum_{n in split} Kn[m,n]*V[c,n]
// ---------------------------------------------------------------------------
__global__ __launch_bounds__(256) void k_matmma()
{
    __shared__ __align__(16) float SA[2][64*SAS];
    __shared__ __align__(16) float SB[2][128*SAS];

    const int tid = threadIdx.x, lane = tid & 31, wid = tid >> 5;
    const int ct = blockIdx.x, sp = blockIdx.y, b = blockIdx.z;
    const int wm = wid & 1, wn = wid >> 1;

    const int j = lane >> 3, r = lane & 7;
    const int aRow = wm*32 + (j & 1)*8 + r;
    const int aCol = (j >> 1)*4;
    const int bRow = wn*32 + (j >> 1)*8 + r;
    const int bCol = (j & 1)*4;

    const float* Ag = g_P + ((size_t)b*PR_ + 64)*N_ + sp*512;            // Kn
    const float* Bg = g_P + ((size_t)b*PR_ + 128 + ct*128)*N_ + sp*512;  // V

    float acc[2][4][4];
    #pragma unroll
    for (int mi=0;mi<2;mi++)
        #pragma unroll
        for (int ni=0;ni<4;ni++)
            #pragma unroll
            for (int q=0;q<4;q++) acc[mi][ni][q] = 0.f;

    {
        int row = tid >> 2, cg = tid & 3;
        *(float4*)&SA[0][row*SAS + cg*4] = round4(*(const float4*)(Ag + (size_t)row*N_ + cg*4));
        #pragma unroll
        for (int s=0;s<2;s++){
            int g = tid + s*256;
            int br = g >> 2, bcg = g & 3;
            *(float4*)&SB[0][br*SAS + bcg*4] = round4(*(const float4*)(Bg + (size_t)br*N_ + bcg*4));
        }
    }
    __syncthreads();

    const uint32_t saB[2] = { smem_u32(&SA[0][0]), smem_u32(&SA[1][0]) };
    const uint32_t sbB[2] = { smem_u32(&SB[0][0]), smem_u32(&SB[1][0]) };

    for (int ch = 0; ch < 32; ch++){
        const int buf = ch & 1;
        float4 pa, pb[2];
        if (ch + 1 < 32){
            int k0 = (ch+1)*BKC;
            int row = tid >> 2, cg = tid & 3;
            pa = *(const float4*)(Ag + (size_t)row*N_ + k0 + cg*4);
            #pragma unroll
            for (int s=0;s<2;s++){
                int g = tid + s*256;
                int br = g >> 2, bcg = g & 3;
                pb[s] = *(const float4*)(Bg + (size_t)br*N_ + k0 + bcg*4);
            }
        }

        #pragma unroll
        for (int ks = 0; ks < 2; ks++){
            uint32_t a[2][4], bb[2][4];
            #pragma unroll
            for (int mi=0;mi<2;mi++){
                uint32_t addr = saB[buf] + (uint32_t)((aRow + mi*16)*SAS + ks*8 + aCol)*4;
                LDSM_X4(a[mi][0],a[mi][1],a[mi][2],a[mi][3], addr);
            }
            #pragma unroll
            for (int nt=0;nt<2;nt++){
                uint32_t addr = sbB[buf] + (uint32_t)(((bRow + nt*16)*SAS) + ks*8 + bCol)*4;
                LDSM_X4(bb[nt][0],bb[nt][1],bb[nt][2],bb[nt][3], addr);
            }
            #pragma unroll
            for (int mi=0;mi<2;mi++)
                #pragma unroll
                for (int nt=0;nt<2;nt++){
                    MMA_TF32(acc[mi][nt*2+0], a[mi], bb[nt][0], bb[nt][1]);
                    MMA_TF32(acc[mi][nt*2+1], a[mi], bb[nt][2], bb[nt][3]);
                }
        }

        if (ch + 1 < 32){
            const int nb = buf ^ 1;
            int row = tid >> 2, cg = tid & 3;
            *(float4*)&SA[nb][row*SAS + cg*4] = round4(pa);
            #pragma unroll
            for (int s=0;s<2;s++){
                int g = tid + s*256;
                int br = g >> 2, bcg = g & 3;
                *(float4*)&SB[nb][br*SAS + bcg*4] = round4(pb[s]);
            }
        }
        __syncthreads();
    }

    const int base_col = ct*128 + wn*32 + (lane & 3)*2;
    float* pbase = g_part + (((size_t)sp*B_ + b)*CQ_)*C_;
    #pragma unroll
    for (int mi=0;mi<2;mi++){
        int m_lo = wm*32 + mi*16 + (lane >> 2);
        int m_hi = m_lo + 8;
        #pragma unroll
        for (int ni=0;ni<4;ni++){
            int col = base_col + ni*8;
            *(float2*)(pbase + (size_t)m_lo*C_ + col) = make_float2(acc[mi][ni][0], acc[mi][ni][1]);
            *(float2*)(pbase + (size_t)m_hi*C_ + col) = make_float2(acc[mi][ni][2], acc[mi][ni][3]);
        }
    }
}

// float4 reduction of split-K partials (deterministic fixed order)
__global__ void k_matreduce()
{
    int idx = (blockIdx.x*256 + threadIdx.x)*4;
    float4 s = *(const float4*)(g_part + idx);
    #pragma unroll
    for (int sp = 1; sp < NSPLIT; sp++){
        float4 v = *(const float4*)(g_part + (size_t)sp*B_*CQ_*C_ + idx);
        s.x += v.x; s.y += v.y; s.z += v.z; s.w += v.w;
    }
    *(float4*)(g_matrix + idx) = s;
}

// ---------------------------------------------------------------------------
// Kernel 4 via TF32 mma: out[b,c,n] = g*tailor[n]*(Vsum[c] + sum_m Qn[m,n]*M[m,c])
// CTA covers 64c x 128n (two 64n passes, SA + A-frags reused).  tailor is
// computed IN-KERNEL per n-pass from the staged (tf32) Qn tile + Ksum.
// ---------------------------------------------------------------------------
#define FS 68    // 64 + 4 pad -> conflict-free LDSM

__global__ __launch_bounds__(256) void k_finalmma(const float* __restrict__ gamma,
                                                  float* __restrict__ out)
{
    __shared__ __align__(16) float SA[64*FS];   // [c_local][m]
    __shared__ __align__(16) float SB[64*FS];   // [n_local][m]
    __shared__ float SKsum[64];
    __shared__ float STail[64];

    const int tid = threadIdx.x, lane = tid & 31, wid = tid >> 5;
    const int n0 = blockIdx.x*128, c0 = blockIdx.y*64, b = blockIdx.z;
    const int wm = wid & 3, wn = wid >> 2;      // warp tile 16c x 32n per pass

    if (tid < 64) SKsum[tid] = g_Ksum[b*CQ_ + tid] + EPSV;

    // stage SA (matrix tile, transposed [c][m])
    #pragma unroll
    for (int s=0;s<4;s++){
        int id = tid + s*256;
        int m = id & 63, cg = id >> 6;
        float4 v = round4(*(const float4*)(g_matrix + ((size_t)b*CQ_ + m)*C_ + c0 + cg*4));
        SA[(cg*4+0)*FS + m] = v.x;
        SA[(cg*4+1)*FS + m] = v.y;
        SA[(cg*4+2)*FS + m] = v.z;
        SA[(cg*4+3)*FS + m] = v.w;
    }
    // stage SB for n-half 0
    #pragma unroll
    for (int s=0;s<4;s++){
        int id = tid + s*256;
        int m = id & 63, ng = id >> 6;
        float4 v = round4(*(const float4*)(g_P + ((size_t)b*PR_ + m)*N_ + n0 + ng*4));
        SB[(ng*4+0)*FS + m] = v.x;
        SB[(ng*4+1)*FS + m] = v.y;
        SB[(ng*4+2)*FS + m] = v.z;
        SB[(ng*4+3)*FS + m] = v.w;
    }
    __syncthreads();

    const uint32_t saB = smem_u32(&SA[0]);
    const uint32_t sbB = smem_u32(&SB[0]);
    const int j = lane >> 3, r = lane & 7;
    const int aRow = wm*16 + (j & 1)*8 + r;
    const int aCol = (j >> 1)*4;
    const int bRow = wn*32 + (j >> 1)*8 + r;
    const int bCol = (j & 1)*4;

    // hoist all A fragments (SA reused by both passes)
    uint32_t a[8][4];
    #pragma unroll
    for (int ks = 0; ks < 8; ks++){
        uint32_t addr = saB + (uint32_t)(aRow*FS + ks*8 + aCol)*4;
        LDSM_X4(a[ks][0],a[ks][1],a[ks][2],a[ks][3], addr);
    }

    const float g = gamma[0];
    const int c_lo = c0 + wm*16 + (lane >> 2);
    const int c_hi = c_lo + 8;
    const float vs_lo = g_Vsum[b*C_ + c_lo];
    const float vs_hi = g_Vsum[b*C_ + c_hi];
    float* o_lo = out + ((size_t)b*C_ + c_lo)*N_;
    float* o_hi = out + ((size_t)b*C_ + c_hi)*N_;

    #pragma unroll
    for (int np = 0; np < 2; np++){
        // tailor for this n-half from staged Qn tile + Ksum
        {
            int nl = tid >> 2, part = tid & 3;
            float s = 0.f;
            #pragma unroll
            for (int i = 0; i < 16; i++){
                int m = part*16 + i;
                s = fmaf(SB[nl*FS + m], SKsum[m], s);
            }
            s += __shfl_xor_sync(0xFFFFFFFF, s, 1);
            s += __shfl_xor_sync(0xFFFFFFFF, s, 2);
            if (part == 0) STail[nl] = 1.f / (4096.f + s);
        }
        __syncthreads();

        float acc[4][4];
        #pragma unroll
        for (int ni=0;ni<4;ni++)
            #pragma unroll
            for (int q=0;q<4;q++) acc[ni][q] = 0.f;

        #pragma unroll
        for (int ks = 0; ks < 8; ks++){
            uint32_t bb[2][4];
            #pragma unroll
            for (int nt=0;nt<2;nt++){
                uint32_t addr = sbB + (uint32_t)((bRow + nt*16)*FS + ks*8 + bCol)*4;
                LDSM_X4(bb[nt][0],bb[nt][1],bb[nt][2],bb[nt][3], addr);
            }
            #pragma unroll
            for (int nt=0;nt<2;nt++){
                MMA_TF32(acc[nt*2+0], a[ks], bb[nt][0], bb[nt][1]);
                MMA_TF32(acc[nt*2+1], a[ks], bb[nt][2], bb[nt][3]);
            }
        }

        const int nloc0 = wn*32 + (lane & 3)*2;
        const int base_n = n0 + np*64 + nloc0;
        #pragma unroll
        for (int ni=0;ni<4;ni++){
            int n = base_n + ni*8;
            float t0 = STail[nloc0 + ni*8]*g, t1 = STail[nloc0 + ni*8 + 1]*g;
            *(float2*)(o_lo + n) = make_float2(t0*(vs_lo + acc[ni][0]), t1*(vs_lo + acc[ni][1]));
            *(float2*)(o_hi + n) = make_float2(t0*(vs_hi + acc[ni][2]), t1*(vs_hi + acc[ni][3]));
        }

        if (np == 0){
            __syncthreads();
            // restage SB for n-half 1
            #pragma unroll
            for (int s=0;s<4;s++){
                int id = tid + s*256;
                int m = id & 63, ng = id >> 6;
                float4 v = round4(*(const float4*)(g_P + ((size_t)b*PR_ + m)*N_ + n0 + 64 + ng*4));
                SB[(ng*4+0)*FS + m] = v.x;
                SB[(ng*4+1)*FS + m] = v.y;
                SB[(ng*4+2)*FS + m] = v.z;
                SB[(ng*4+3)*FS + m] = v.w;
            }
            __syncthreads();
        }
    }
}

// ---------------------------------------------------------------------------
extern "C" void kernel_launch(void* const* d_in, const int* in_sizes, int n_in,
                              void* d_out, int out_size)
{
    const float* x     = (const float*)d_in[0];
    const float* Wq    = (const float*)d_in[1];
    const float* bq    = (const float*)d_in[2];
    const float* Wk    = (const float*)d_in[3];
    const float* bk    = (const float*)d_in[4];
    const float* Wv    = (const float*)d_in[5];
    const float* bv    = (const float*)d_in[6];
    const float* gamma = (const float*)d_in[7];
    float* out = (float*)d_out;

    k_convW    <<<(PR_*C_)/256, 256>>>(Wq, bq, Wk, bk, Wv, bv);
    k_projmma  <<<dim3(32,5,8), 256>>>(x);
    k_rsreduce <<<18, 256>>>();
    k_matmma   <<<dim3(4,8,8),  256>>>();
    k_matreduce<<<(B_*CQ_*C_)/1024, 256>>>();
    k_finalmma <<<dim3(32,8,8), 256>>>(gamma, out);
}